// round 9
// baseline (speedup 1.0000x reference)
#include <cuda_runtime.h>
#include <cuda_bf16.h>

#define NN 320
#define DD 256

// Scratch (allocation-free device globals)
__device__ float  g_L[NN * NN];       // logits (bit-exact symmetric)
__device__ float  g_E[NN * NN];       // exp(logits)
__device__ float  g_ys[NN];           // sorted y_times
__device__ int    g_perm[NN];         // sorted pos -> original index
__device__ int    g_se[NN];           // event class in sorted order
__device__ int    g_gt[NN];           // per k: count of !(ys-yk > 0)
__device__ int    g_geq[NN];          // per k: count of (ys-yk < 0)
__device__ float2 g_P[NN * (NN + 1)]; // per-row class-split E prefix sums
__device__ int    g_cnt[NN + 1];      // class-count prefix, packed c1<<10 | c0
__device__ float  g_loss[NN];
__device__ float  g_pos[NN];
__device__ int    g_ctr;              // lossk completion (monotone across replays)

// TABLE rows packed: weight code c in {0,1,2} (weight = c*0.5) at bits [2v+1:2v],
// v = td + 3*e, td in {1(lower),2(middle),3(upper)}.
__constant__ int c_rb[7] = {8852, 5460, 4692, 5460, 5716, 4436, 8852};

typedef unsigned long long ull;

// Packed fp32x2 helpers (sm_103a FFMA2 path — only reachable via PTX).
// acc += (x + ny)^2 elementwise on a packed pair; x + (-y) is IEEE-identical
// to x - y.
__device__ __forceinline__ void dsq_acc(ull& acc, ull x, ull ny) {
    ull d;
    asm("add.rn.f32x2 %0, %1, %2;" : "=l"(d) : "l"(x), "l"(ny));
    asm("fma.rn.f32x2 %0, %1, %1, %0;" : "+l"(acc) : "l"(d));
}
__device__ __forceinline__ float dsum(ull acc) {
    unsigned lo, hi;
    asm("mov.b64 {%0, %1}, %2;" : "=r"(lo), "=r"(hi) : "l"(acc));
    return __uint_as_float(lo) + __uint_as_float(hi);
}

// SMEM (float2 units): sA [32][130], sB [32][130] (negated), partials 3*64*17
#define RSTRIDE 130                     // 1040 B row: 16B-aligned, bank step 4
#define SA_F2   (32 * RSTRIDE)          // 4160
#define PART_F2 (3 * 64 * 17)           // 3264
#define SMEM_BYTES ((2 * SA_F2 + PART_F2) * 8 + 256)

// ---------------------------------------------------------------------------
// Kernel 1: blocks 0..99 = 32x32 distance tiles, 256 threads (8,8,4). Smem
// tiles stay ROW-MAJOR (same layout as global) -> staging stores are
// consecutive-address (conflict-free). tz K-splits the 128 d-pairs into 4
// slices; 4x4 micro-tiles at stride-8 offsets make all compute LDS
// conflict-free (A banks 4*ty+c broadcast over tx; B banks 4*tx+c broadcast
// over ty). Subtract-form squared distance: exact, diagonal accumulates
// exactly +0 (matches the reference no-op row-max: diag logit 0 == row max);
// slice partials combined in fixed order -> deterministic.
// Block 100 = exact rank sort + run bounds.
// ---------------------------------------------------------------------------
__global__ void __launch_bounds__(256, 1)
fused_kernel(const float* __restrict__ F,
             const float* __restrict__ yt,
             const int* __restrict__ ye) {
    extern __shared__ char smem_raw[];
    float2* sA = (float2*)smem_raw;                 // [32][130]
    float2* sB = sA + SA_F2;                        // negated B tile
    float2* s_part = sB + SA_F2;                    // [(tz-1)*64+pos][17]
    float*  s_y = (float*)smem_raw;                 // sort-block overlay

    int tx = threadIdx.x, ty = threadIdx.y, tz = threadIdx.z;   // 8,8,4
    int tid = (tz * 8 + ty) * 8 + tx;
    int b = blockIdx.x;

    if (b == 100) {
        // --- sort / bounds: O(N) exact counts per anchor ---
        for (int e = tid; e < NN; e += 256) s_y[e] = yt[e];
        __syncthreads();
        for (int e = tid; e < NN; e += 256) {
            float v = s_y[e];
            int rank = 0, gt = 0, geq = 0;
#pragma unroll 8
            for (int j = 0; j < NN; j++) {
                float w = s_y[j];
                float d = w - v;                       // same float expr as reference pld
                rank += (w < v) || (w == v && j < e);  // unique tie-broken rank
                gt  += !(d > 0.0f);
                geq += (d < 0.0f);
            }
            g_ys[rank] = v; g_perm[rank] = e; g_se[rank] = __ldg(&ye[e]);
            g_gt[e] = gt; g_geq[e] = geq;
        }
        return;
    }

    int bi = (b / 10) * 32, bj = (b % 10) * 32;

    // Stage A (as-is) and B (negated) row-major: coalesced LDG.128 +
    // consecutive-address STS.128 (conflict-free). FULL tile: 2048 float4
    // slots = 32 rows x 64 float4 (256 floats) per tile.
#pragma unroll
    for (int v = 0; v < 8; v++) {
        int fidx = v * 256 + tid;     // 0..2047 float4 slots per tile
        int row = fidx >> 6;          // 64 float4 per row
        int c4 = fidx & 63;
        float4 av = *(const float4*)(F + (bi + row) * DD + c4 * 4);
        float4 bv = *(const float4*)(F + (bj + row) * DD + c4 * 4);
        ((float4*)(sA + row * RSTRIDE))[c4] = av;
        ((float4*)(sB + row * RSTRIDE))[c4] = make_float4(-bv.x, -bv.y, -bv.z, -bv.w);
    }
    __syncthreads();

    // Slice tz covers dpairs [32tz, 32tz+32); micro-tile i = ty+8a, j = tx+8c.
    const float2* A0 = sA + (ty +  0) * RSTRIDE + tz * 32;
    const float2* A1 = sA + (ty +  8) * RSTRIDE + tz * 32;
    const float2* A2 = sA + (ty + 16) * RSTRIDE + tz * 32;
    const float2* A3 = sA + (ty + 24) * RSTRIDE + tz * 32;
    const float2* B0 = sB + (tx +  0) * RSTRIDE + tz * 32;
    const float2* B1 = sB + (tx +  8) * RSTRIDE + tz * 32;
    const float2* B2 = sB + (tx + 16) * RSTRIDE + tz * 32;
    const float2* B3 = sB + (tx + 24) * RSTRIDE + tz * 32;

    ull acc[4][4];
#pragma unroll
    for (int a = 0; a < 4; a++)
#pragma unroll
        for (int c = 0; c < 4; c++) acc[a][c] = 0ull;

#pragma unroll
    for (int q = 0; q < 32; q++) {
        ull x0 = *(const ull*)(A0 + q);
        ull x1 = *(const ull*)(A1 + q);
        ull x2 = *(const ull*)(A2 + q);
        ull x3 = *(const ull*)(A3 + q);
        ull y0 = *(const ull*)(B0 + q);
        ull y1 = *(const ull*)(B1 + q);
        ull y2 = *(const ull*)(B2 + q);
        ull y3 = *(const ull*)(B3 + q);
        dsq_acc(acc[0][0], x0, y0); dsq_acc(acc[0][1], x0, y1);
        dsq_acc(acc[0][2], x0, y2); dsq_acc(acc[0][3], x0, y3);
        dsq_acc(acc[1][0], x1, y0); dsq_acc(acc[1][1], x1, y1);
        dsq_acc(acc[1][2], x1, y2); dsq_acc(acc[1][3], x1, y3);
        dsq_acc(acc[2][0], x2, y0); dsq_acc(acc[2][1], x2, y1);
        dsq_acc(acc[2][2], x2, y2); dsq_acc(acc[2][3], x2, y3);
        dsq_acc(acc[3][0], x3, y0); dsq_acc(acc[3][1], x3, y1);
        dsq_acc(acc[3][2], x3, y2); dsq_acc(acc[3][3], x3, y3);
    }

    int pos = ty * 8 + tx;
    __syncthreads();                       // tiles no longer needed
    if (tz > 0) {
        float2* dst = s_part + ((tz - 1) * 64 + pos) * 17;
#pragma unroll
        for (int a = 0; a < 4; a++)
#pragma unroll
            for (int c = 0; c < 4; c++) {
                ull v = acc[a][c];
                dst[a * 4 + c] = *(float2*)&v;
            }
    }
    __syncthreads();
    if (tz == 0) {
#pragma unroll
        for (int a = 0; a < 4; a++) {
            int i = ty + 8 * a;
#pragma unroll
            for (int c = 0; c < 4; c++) {
                int j = tx + 8 * c;
                ull v = acc[a][c];
                float2 s = *(float2*)&v;
                // fixed combine order over slices -> deterministic
#pragma unroll
                for (int sidx = 0; sidx < 3; sidx++) {
                    float2 p = s_part[(sidx * 64 + pos) * 17 + a * 4 + c];
                    s.x += p.x; s.y += p.y;
                }
                float d2 = s.x + s.y;      // >= 0 by construction; diag == +0
                float L = -0.5f * sqrtf(d2);
                g_L[(bi + i) * NN + (bj + j)] = L;
                g_E[(bi + i) * NN + (bj + j)] = __expf(L);
            }
        }
    }
}

// ---------------------------------------------------------------------------
// Kernel 2: per-row class-split prefix sums (warp-shuffle scan). Block 0 also
// builds the global class-count prefix.
// ---------------------------------------------------------------------------
__global__ void scan_kernel() {
    __shared__ float ws0[10], ws1[10], wo0[10], wo1[10];
    __shared__ int   wsi[10], woi[10];
    int i = blockIdx.x, t = threadIdx.x;
    int lane = t & 31, w = t >> 5;

    int pj = g_perm[t];
    int cls = g_se[t];
    float Ev = (pj == i) ? 0.f : __ldg(&g_E[i * NN + pj]);   // eye mask folded
    float x0 = cls ? 0.f : Ev;
    float x1 = cls ? Ev : 0.f;
    int   xc = cls ? (1 << 10) : 1;

#pragma unroll
    for (int off = 1; off < 32; off <<= 1) {
        float a0 = __shfl_up_sync(0xffffffffu, x0, off);
        float a1 = __shfl_up_sync(0xffffffffu, x1, off);
        int   ac = __shfl_up_sync(0xffffffffu, xc, off);
        if (lane >= off) { x0 += a0; x1 += a1; xc += ac; }
    }
    if (lane == 31) { ws0[w] = x0; ws1[w] = x1; wsi[w] = xc; }
    __syncthreads();
    if (t == 0) {
        float r0 = 0.f, r1 = 0.f; int ri = 0;
#pragma unroll
        for (int q = 0; q < 10; q++) {
            wo0[q] = r0; wo1[q] = r1; woi[q] = ri;
            r0 += ws0[q]; r1 += ws1[q]; ri += wsi[q];
        }
    }
    __syncthreads();
    x0 += wo0[w]; x1 += wo1[w];
    float2* Prow = g_P + i * (NN + 1);
    Prow[t + 1] = make_float2(x0, x1);
    if (t == 0) Prow[0] = make_float2(0.f, 0.f);
    if (i == 0) {
        g_cnt[t + 1] = xc + woi[w];
        if (t == 0) g_cnt[0] = 0;
    }
}

// ---------------------------------------------------------------------------
// Kernel 3: block per anchor k, thread per row i. 2 binary searches + prefix
// assembly; exact integer-count validity; block reduce -> loss_k; last block
// (monotone counter modulo NN) produces the final scalar deterministically.
// ---------------------------------------------------------------------------
__global__ void lossk_kernel(const float* __restrict__ yt,
                             const int* __restrict__ ye,
                             float* __restrict__ out) {
    __shared__ float s_ys[NN];
    __shared__ int   s_cnt[NN + 1];
    __shared__ int   s_rb[7];
    __shared__ float rS[10], rC[10];
    __shared__ int   s_last;

    int k = blockIdx.x, t = threadIdx.x;
    int lane = t & 31, w = t >> 5;
    s_ys[t] = g_ys[t];
    s_cnt[t] = g_cnt[t];
    if (t == 0) s_cnt[NN] = g_cnt[NN];
    if (t < 7) s_rb[t] = c_rb[t];
    __syncthreads();

    float yk = __ldg(&yt[k]);
    int   ek = __ldg(&ye[k]);
    int   gt = g_gt[k], geq = g_geq[k];

    int i = t;
    float yi = yt[i];
    int   ei = ye[i];
    float pi = yi - yk;
    float a = fabsf(pi), na = -a;

    int base = ei + 10 * ek;
    int cid = (pi > 0.f) ? base : ((pi < 0.f) ? -base : 0);
    int cidx = (cid == -11) ? 0 : (cid == -10) ? 1 : (cid == -1) ? 2 :
               (cid == 0)   ? 3 : (cid == 1)   ? 4 : (cid == 10) ? 5 : 6;
    int rb = s_rb[cidx];

    // hi: first m with ys[m]-yk > a  (identical float expr as reference)
    int first = 0, count = NN;
    while (count > 0) {
        int half = count >> 1, mid = first + half;
        if (!(s_ys[mid] - yk > a)) { first = mid + 1; count -= half + 1; }
        else count = half;
    }
    int hi = first;
    // lo: first m with !(ys[m]-yk < -a)
    first = 0; count = NN;
    while (count > 0) {
        int half = count >> 1, mid = first + half;
        if (s_ys[mid] - yk < na) { first = mid + 1; count -= half + 1; }
        else count = half;
    }
    int lo = first;

    const float2* Prow = g_P + i * (NN + 1);
    float2 Pend = Prow[NN], Phi = Prow[hi], Plo = Prow[lo];
    float2 Pgt = Prow[gt], Pgq = Prow[geq];
    float SU0 = Pend.x - Phi.x, SU1 = Pend.y - Phi.y;
    float SL0 = Plo.x,          SL1 = Plo.y;
    float SM0 = (Phi.x - Plo.x) - (Pgt.x - Pgq.x);
    float SM1 = (Phi.y - Plo.y) - (Pgt.y - Pgq.y);

    float w10 = (float)((rb >> 2)  & 3), w20 = (float)((rb >> 4)  & 3), w30 = (float)((rb >> 6)  & 3);
    float w11 = (float)((rb >> 8)  & 3), w21 = (float)((rb >> 10) & 3), w31 = (float)((rb >> 12) & 3);
    float denom = 0.5f * (w10 * SL0 + w11 * SL1 + w20 * SM0 + w21 * SM1 + w30 * SU0 + w31 * SU1);

    // Exact integer validity: counts of positive-weight elements.
    int cU = s_cnt[NN] - s_cnt[hi];
    int cL = s_cnt[lo];
    int cM = (s_cnt[hi] - s_cnt[lo]) - (s_cnt[gt] - s_cnt[geq]);
    if (pi != 0.f) cM -= (ei ? (1 << 10) : 1);   // i sits in middle, weight 0 (eye)
    int nz = rb | (rb >> 1);
    int vsum = ((nz >> 2) & 1) * (cL & 1023) + ((nz >> 8)  & 1) * (cL >> 10)
             + ((nz >> 4) & 1) * (cM & 1023) + ((nz >> 10) & 1) * (cM >> 10)
             + ((nz >> 6) & 1) * (cU & 1023) + ((nz >> 12) & 1) * (cU >> 10);
    bool valid = (vsum > 0) && (i != k);

    float res = valid ? (__ldg(&g_L[k * NN + i]) - __logf(denom)) : 0.f;  // L symmetric
    float c   = valid ? 1.f : 0.f;

#pragma unroll
    for (int sh = 16; sh > 0; sh >>= 1) {
        res += __shfl_xor_sync(0xffffffffu, res, sh);
        c   += __shfl_xor_sync(0xffffffffu, c,   sh);
    }
    if (lane == 0) { rS[w] = res; rC[w] = c; }
    __syncthreads();
    if (t == 0) {
        float S = 0.f, C = 0.f;
#pragma unroll
        for (int q = 0; q < 10; q++) { S += rS[q]; C += rC[q]; }
        g_loss[k] = (C > 0.f) ? (-S / C) : 0.f;
        g_pos[k]  = (C > 0.f) ? 1.f : 0.f;
        __threadfence();
        int old = atomicAdd(&g_ctr, 1);
        s_last = ((old % NN) == NN - 1);   // monotone: no reset between replays
    }
    __syncthreads();
    if (s_last) {
        float sa = __ldcg(&g_loss[t]), sb = __ldcg(&g_pos[t]);
#pragma unroll
        for (int sh = 16; sh > 0; sh >>= 1) {
            sa += __shfl_xor_sync(0xffffffffu, sa, sh);
            sb += __shfl_xor_sync(0xffffffffu, sb, sh);
        }
        if (lane == 0) { rS[w] = sa; rC[w] = sb; }
        __syncthreads();
        if (t == 0) {
            float S = 0.f, P = 0.f;
#pragma unroll
            for (int q = 0; q < 10; q++) { S += rS[q]; P += rC[q]; }
            out[0] = S / P;
        }
    }
}

extern "C" void kernel_launch(void* const* d_in, const int* in_sizes, int n_in,
                              void* d_out, int out_size) {
    const float* features = (const float*)d_in[0];   // [320, 256] f32
    const float* y_times  = (const float*)d_in[1];   // [320] f32
    const int*   y_events = (const int*)d_in[2];     // [320] i32
    float* out = (float*)d_out;

    cudaFuncSetAttribute(fused_kernel,
                         cudaFuncAttributeMaxDynamicSharedMemorySize, SMEM_BYTES);

    fused_kernel<<<101, dim3(8, 8, 4), SMEM_BYTES>>>(features, y_times, y_events);
    scan_kernel<<<NN, NN>>>();
    lossk_kernel<<<NN, NN>>>(y_times, y_events, out);
}